// round 1
// baseline (speedup 1.0000x reference)
#include <cuda_runtime.h>

// Problem constants
#define B_   2
#define S_   2048
#define D_   1024
#define H_   16
#define P_   2048
#define T_   4096          // P + S
#define D3_  3072          // 3*D
#define OUT_OFF (B_*S_*D_) // 4,194,304 floats: start of `present` in d_out

// ---------------------------------------------------------------------------
// Scratch (device globals; no runtime allocation allowed)
// ---------------------------------------------------------------------------
__device__ float g_qkv[(size_t)B_ * S_ * D3_];     // [B*S, 3D]   = 12.58M floats
__device__ float g_qt [(size_t)B_ * H_ * 64 * S_]; // [B*H][64][S] (Q^T, pre-scaled by 1/8)
__device__ float g_kt [(size_t)B_ * H_ * 64 * T_]; // [B*H][64][T] (K^T incl. cache)
__device__ float g_ctx[(size_t)B_ * S_ * D_];      // merged context [B*S, D]

// ---------------------------------------------------------------------------
// SGEMM with bias: C[M,N] = A[M,K] @ B[K,N] + bias[N]
// BM=BN=128, BK=16, 256 threads, 8x8 per thread (4+4 split), float4 frags.
// ---------------------------------------------------------------------------
__global__ __launch_bounds__(256) void sgemm_bias(
    const float* __restrict__ A, const float* __restrict__ Bm,
    const float* __restrict__ bias, float* __restrict__ C,
    int M, int N, int K)
{
    __shared__ float As[16][132];   // transposed A tile, +4 pad
    __shared__ float Bs[16][128];

    const int tid = threadIdx.x;
    const int tx = tid & 15;        // col group
    const int ty = tid >> 4;        // row group
    const int blockRow = blockIdx.y << 7;
    const int blockCol = blockIdx.x << 7;

    float acc[8][8];
#pragma unroll
    for (int i = 0; i < 8; i++)
#pragma unroll
        for (int j = 0; j < 8; j++) acc[i][j] = 0.f;

    for (int k0 = 0; k0 < K; k0 += 16) {
        // load A tile (128x16) transposed into As
#pragma unroll
        for (int i = 0; i < 2; i++) {
            int f  = tid + (i << 8);       // 0..511 float4 slots
            int r  = f >> 2;               // 0..127
            int c4 = (f & 3) << 2;         // 0,4,8,12
            float4 v = *(const float4*)(A + (size_t)(blockRow + r) * K + k0 + c4);
            As[c4 + 0][r] = v.x; As[c4 + 1][r] = v.y;
            As[c4 + 2][r] = v.z; As[c4 + 3][r] = v.w;
        }
        // load B tile (16x128)
#pragma unroll
        for (int i = 0; i < 2; i++) {
            int f  = tid + (i << 8);
            int r  = f >> 5;               // 0..15
            int c4 = (f & 31) << 2;        // 0..124
            *(float4*)&Bs[r][c4] =
                *(const float4*)(Bm + (size_t)(k0 + r) * N + blockCol + c4);
        }
        __syncthreads();

#pragma unroll
        for (int kk = 0; kk < 16; kk++) {
            float a[8], bb[8];
            *(float4*)&a[0]  = *(float4*)&As[kk][ty * 4];
            *(float4*)&a[4]  = *(float4*)&As[kk][ty * 4 + 64];
            *(float4*)&bb[0] = *(float4*)&Bs[kk][tx * 4];
            *(float4*)&bb[4] = *(float4*)&Bs[kk][tx * 4 + 64];
#pragma unroll
            for (int i = 0; i < 8; i++)
#pragma unroll
                for (int j = 0; j < 8; j++)
                    acc[i][j] += a[i] * bb[j];
        }
        __syncthreads();
    }

    // epilogue: add bias, write
#pragma unroll
    for (int ih = 0; ih < 2; ih++) {
#pragma unroll
        for (int i = 0; i < 4; i++) {
            int row = blockRow + ih * 64 + ty * 4 + i;
#pragma unroll
            for (int jh = 0; jh < 2; jh++) {
                int col = blockCol + jh * 64 + tx * 4;
                float4 o;
                o.x = acc[ih * 4 + i][jh * 4 + 0] + bias[col + 0];
                o.y = acc[ih * 4 + i][jh * 4 + 1] + bias[col + 1];
                o.z = acc[ih * 4 + i][jh * 4 + 2] + bias[col + 2];
                o.w = acc[ih * 4 + i][jh * 4 + 3] + bias[col + 3];
                *(float4*)(C + (size_t)row * N + col) = o;
            }
        }
    }
}

// ---------------------------------------------------------------------------
// Build `present` [B,2,H,T,64] in d_out from past_layer + new K/V in qkv.
// Fully vectorized float4, coalesced.
// ---------------------------------------------------------------------------
__global__ void build_present(const float4* __restrict__ past4,
                              const float4* __restrict__ qkv4,
                              float4* __restrict__ pres4)
{
    int i = blockIdx.x * blockDim.x + threadIdx.x;   // 4,194,304 float4s
    int d4  = i & 15;
    int j   = i >> 4;
    int p   = j & (T_ - 1);
    int chh = j >> 12;
    int h = chh & (H_ - 1);
    int c = (chh >> 4) & 1;
    int b = chh >> 5;

    float4 v;
    if (p < P_) {
        v = past4[(((size_t)((b * 2 + c) * H_ + h) * P_ + p) << 4) + d4];
    } else {
        int s = p - P_;
        // qkv float4 index: ((b*S+s)*3072 + (c+1)*1024 + h*64)/4 + d4
        v = qkv4[(size_t)(b * S_ + s) * 768 + (c + 1) * 256 + h * 16 + d4];
    }
    pres4[i] = v;
}

// ---------------------------------------------------------------------------
// Transpose Q: qkv[b,s, h*64+d] -> qt[(b*H+h)*64+d][s], scaled by 1/sqrt(64).
// ---------------------------------------------------------------------------
__global__ __launch_bounds__(256) void transpose_q(
    const float* __restrict__ qkv, float* __restrict__ qt)
{
    __shared__ float t[64][65];
    const int tid = threadIdx.x;
    const int bh = blockIdx.y;
    const int b = bh >> 4, h = bh & 15;
    const int s0 = blockIdx.x << 6;
    const int col = tid & 63, rr = tid >> 6;

#pragma unroll
    for (int i = 0; i < 16; i++) {
        int r = (i << 2) + rr;
        t[r][col] = qkv[(size_t)(b * S_ + s0 + r) * D3_ + h * 64 + col] * 0.125f;
    }
    __syncthreads();
#pragma unroll
    for (int i = 0; i < 16; i++) {
        int d = (i << 2) + rr;
        qt[((size_t)bh * 64 + d) * S_ + s0 + col] = t[col][d];
    }
}

// ---------------------------------------------------------------------------
// Transpose K from present: present[b,0,h,p,d] -> kt[(b*H+h)*64+d][p]
// ---------------------------------------------------------------------------
__global__ __launch_bounds__(256) void transpose_k(
    const float* __restrict__ present, float* __restrict__ kt)
{
    __shared__ float t[64][65];
    const int tid = threadIdx.x;
    const int bh = blockIdx.y;
    const int b = bh >> 4, h = bh & 15;
    const int p0 = blockIdx.x << 6;
    const int col = tid & 63, rr = tid >> 6;
    const float* src = present + ((size_t)(b * 2) * H_ + h) * T_ * 64;

#pragma unroll
    for (int i = 0; i < 16; i++) {
        int r = (i << 2) + rr;
        t[r][col] = src[(size_t)(p0 + r) * 64 + col];
    }
    __syncthreads();
#pragma unroll
    for (int i = 0; i < 16; i++) {
        int d = (i << 2) + rr;
        kt[((size_t)bh * 64 + d) * T_ + p0 + col] = t[col][d];
    }
}

// ---------------------------------------------------------------------------
// Flash attention: streaming softmax over key tiles. BQ=BK=64, 64 threads,
// 8x8 micro-tile per thread. Causal mask applied on diagonal tile only
// (exp underflows to 0 == reference's -1e9 additive mask in fp32).
// smem: 3 x 16KB = 48KB exactly. P tile reuses the K buffer with a
// rotation swizzle addr = row*64 + ((col+row)&63) -> conflict-free reads.
// ---------------------------------------------------------------------------
__global__ __launch_bounds__(64) void flash_kernel(
    const float* __restrict__ Qt, const float* __restrict__ Kt,
    const float* __restrict__ present, float* __restrict__ ctx)
{
    __shared__ float sQ[64 * 64];  // [d][s]
    __shared__ float sK[64 * 64];  // [d][k], reused as P tile
    __shared__ float sV[64 * 64];  // [k][d]

    const int tid = threadIdx.x;
    const int ty = tid >> 3, tx = tid & 7;
    const int bh = blockIdx.y;
    const int b = bh >> 4, h = bh & 15;
    const int qtile = gridDim.x - 1 - blockIdx.x;  // big tiles first
    const int q0 = qtile << 6;

    const float* Qb = Qt + (size_t)bh * 64 * S_ + q0;
    const float* Kb = Kt + (size_t)bh * 64 * T_;
    const float* Vb = present + ((size_t)(b * 2 + 1) * H_ + h) * T_ * 64;

    // load Q tile [d][s] (pre-scaled)
#pragma unroll
    for (int i = 0; i < 16; i++) {
        int f = tid + (i << 6);
        int d = f >> 4, c4 = (f & 15) << 2;
        *(float4*)&sQ[(d << 6) + c4] = *(const float4*)&Qb[(size_t)d * S_ + c4];
    }

    float m[8], l[8], o[8][8];
#pragma unroll
    for (int r = 0; r < 8; r++) {
        m[r] = -1e30f; l[r] = 0.f;
#pragma unroll
        for (int c = 0; c < 8; c++) o[r][c] = 0.f;
    }

    const int nIter = ((P_ + q0) >> 6) + 1;
    for (int it = 0; it < nIter; it++) {
        const int k0 = it << 6;
        __syncthreads();
        // load K tile [d][k] and V tile [k][d]
#pragma unroll
        for (int i = 0; i < 16; i++) {
            int f = tid + (i << 6);
            int d = f >> 4, c4 = (f & 15) << 2;
            *(float4*)&sK[(d << 6) + c4] = *(const float4*)&Kb[(size_t)d * T_ + k0 + c4];
            *(float4*)&sV[(d << 6) + c4] = *(const float4*)&Vb[(size_t)(k0 + d) * 64 + c4];
        }
        __syncthreads();

        // S = Q^T-tile . K-tile  (inner over d, rank-1 updates)
        float s[8][8];
#pragma unroll
        for (int r = 0; r < 8; r++)
#pragma unroll
            for (int c = 0; c < 8; c++) s[r][c] = 0.f;

#pragma unroll 8
        for (int d = 0; d < 64; d++) {
            float a[8], k[8];
            *(float4*)&a[0] = *(float4*)&sQ[(d << 6) + (ty << 3)];
            *(float4*)&a[4] = *(float4*)&sQ[(d << 6) + (ty << 3) + 4];
            *(float4*)&k[0] = *(float4*)&sK[(d << 6) + (tx << 3)];
            *(float4*)&k[4] = *(float4*)&sK[(d << 6) + (tx << 3) + 4];
#pragma unroll
            for (int r = 0; r < 8; r++)
#pragma unroll
                for (int c = 0; c < 8; c++)
                    s[r][c] += a[r] * k[c];
        }

        // causal mask on the diagonal tile (k0 == P + q0)
        if (it == nIter - 1) {
#pragma unroll
            for (int r = 0; r < 8; r++)
#pragma unroll
                for (int c = 0; c < 8; c++)
                    if ((tx << 3) + c > (ty << 3) + r) s[r][c] = -1e30f;
        }

        // online softmax (row groups of 8 lanes share a row -> shfl reduce)
#pragma unroll
        for (int r = 0; r < 8; r++) {
            float tm = s[r][0];
#pragma unroll
            for (int c = 1; c < 8; c++) tm = fmaxf(tm, s[r][c]);
            tm = fmaxf(tm, __shfl_xor_sync(0xffffffffu, tm, 1));
            tm = fmaxf(tm, __shfl_xor_sync(0xffffffffu, tm, 2));
            tm = fmaxf(tm, __shfl_xor_sync(0xffffffffu, tm, 4));
            float mn = fmaxf(m[r], tm);
            float sc = __expf(m[r] - mn);
            float rs = 0.f;
#pragma unroll
            for (int c = 0; c < 8; c++) {
                float p = __expf(s[r][c] - mn);
                s[r][c] = p;
                rs += p;
            }
            rs += __shfl_xor_sync(0xffffffffu, rs, 1);
            rs += __shfl_xor_sync(0xffffffffu, rs, 2);
            rs += __shfl_xor_sync(0xffffffffu, rs, 4);
            l[r] = l[r] * sc + rs;
            m[r] = mn;
#pragma unroll
            for (int c = 0; c < 8; c++) o[r][c] *= sc;
        }

        __syncthreads();
        // write P into sK with rotation swizzle
#pragma unroll
        for (int r = 0; r < 8; r++) {
            int row = (ty << 3) + r;
#pragma unroll
            for (int c = 0; c < 8; c++) {
                int col = (tx << 3) + c;
                sK[(row << 6) + ((col + row) & 63)] = s[r][c];
            }
        }
        __syncthreads();

        // O += P . V   (inner over k)
#pragma unroll 8
        for (int k = 0; k < 64; k++) {
            float v[8], p[8];
            *(float4*)&v[0] = *(float4*)&sV[(k << 6) + (tx << 3)];
            *(float4*)&v[4] = *(float4*)&sV[(k << 6) + (tx << 3) + 4];
#pragma unroll
            for (int r = 0; r < 8; r++) {
                int row = (ty << 3) + r;
                p[r] = sK[(row << 6) + ((k + row) & 63)];
            }
#pragma unroll
            for (int r = 0; r < 8; r++)
#pragma unroll
                for (int c = 0; c < 8; c++)
                    o[r][c] += p[r] * v[c];
        }
    }

    // epilogue: normalize, write merged ctx [b, s, h*64+d]
#pragma unroll
    for (int r = 0; r < 8; r++) {
        float inv = 1.f / l[r];
        int row = q0 + (ty << 3) + r;
        float* dst = ctx + (size_t)(b * S_ + row) * D_ + h * 64 + (tx << 3);
        float4 w0, w1;
        w0.x = o[r][0] * inv; w0.y = o[r][1] * inv;
        w0.z = o[r][2] * inv; w0.w = o[r][3] * inv;
        w1.x = o[r][4] * inv; w1.y = o[r][5] * inv;
        w1.z = o[r][6] * inv; w1.w = o[r][7] * inv;
        *(float4*)dst       = w0;
        *(float4*)(dst + 4) = w1;
    }
}

// ---------------------------------------------------------------------------
// Launch
// ---------------------------------------------------------------------------
extern "C" void kernel_launch(void* const* d_in, const int* in_sizes, int n_in,
                              void* d_out, int out_size)
{
    const float* x      = (const float*)d_in[0];
    // d_in[1] = mask: provably causal, applied analytically -> not read
    const float* past   = (const float*)d_in[2];
    const float* w_attn = (const float*)d_in[3];
    const float* b_attn = (const float*)d_in[4];
    const float* w_proj = (const float*)d_in[5];
    const float* b_proj = (const float*)d_in[6];

    float* out     = (float*)d_out;          // [B,S,D]
    float* present = out + OUT_OFF;          // [B,2,H,T,64]

    void* p;
    float *qkv, *qt, *kt, *ctx;
    cudaGetSymbolAddress(&p, g_qkv); qkv = (float*)p;
    cudaGetSymbolAddress(&p, g_qt);  qt  = (float*)p;
    cudaGetSymbolAddress(&p, g_kt);  kt  = (float*)p;
    cudaGetSymbolAddress(&p, g_ctx); ctx = (float*)p;

    // 1. QKV projection: [4096,1024] @ [1024,3072] + bias
    sgemm_bias<<<dim3(D3_ / 128, (B_ * S_) / 128), 256>>>(
        x, w_attn, b_attn, qkv, B_ * S_, D3_, D_);

    // 2. Assemble present (KV cache concat) directly into d_out
    build_present<<<(B_ * 2 * H_ * T_ * 16) / 256, 256>>>(
        (const float4*)past, (const float4*)qkv, (float4*)present);

    // 3. Transposed operand layouts for attention
    transpose_q<<<dim3(S_ / 64, B_ * H_), 256>>>(qkv, qt);
    transpose_k<<<dim3(T_ / 64, B_ * H_), 256>>>(present, kt);

    // 4. Flash attention -> merged context
    flash_kernel<<<dim3(S_ / 64, B_ * H_), 64>>>(qt, kt, present, ctx);

    // 5. Output projection: [4096,1024] @ [1024,1024] + bias
    sgemm_bias<<<dim3(D_ / 128, (B_ * S_) / 128), 256>>>(
        ctx, w_proj, b_proj, out, B_ * S_, D_, D_);
}

// round 4
// speedup vs baseline: 2.3043x; 2.3043x over previous
#include <cuda_runtime.h>
#include <cuda_bf16.h>

// Problem constants
#define B_   2
#define S_   2048
#define D_   1024
#define H_   16
#define P_   2048
#define T_   4096
#define D3_  3072
#define OUT_OFF (B_*S_*D_)

// ---------------------------------------------------------------------------
// Scratch (device globals; no runtime allocation allowed)
// ---------------------------------------------------------------------------
__device__ float g_qkv[(size_t)B_ * S_ * D3_];
__device__ float g_ctx[(size_t)B_ * S_ * D_];
__device__ __nv_bfloat16 g_wah[(size_t)D3_ * D_];   // w_attn^T hi [N=3072][K=1024]
__device__ __nv_bfloat16 g_wal[(size_t)D3_ * D_];   // w_attn^T lo
__device__ __nv_bfloat16 g_wph[(size_t)D_ * D_];    // w_proj^T hi [1024][1024]
__device__ __nv_bfloat16 g_wpl[(size_t)D_ * D_];    // w_proj^T lo

// ---------------------------------------------------------------------------
// Primitives
// ---------------------------------------------------------------------------
__device__ __forceinline__ void mma_bf16(float* d, const unsigned* a, const unsigned* b) {
    asm volatile(
        "mma.sync.aligned.m16n8k16.row.col.f32.bf16.bf16.f32 "
        "{%0,%1,%2,%3}, {%4,%5,%6,%7}, {%8,%9}, {%0,%1,%2,%3};\n"
        : "+f"(d[0]), "+f"(d[1]), "+f"(d[2]), "+f"(d[3])
        : "r"(a[0]), "r"(a[1]), "r"(a[2]), "r"(a[3]), "r"(b[0]), "r"(b[1]));
}
__device__ __forceinline__ void ldsm_x4(unsigned* r, unsigned addr) {
    asm volatile("ldmatrix.sync.aligned.m8n8.x4.shared.b16 {%0,%1,%2,%3}, [%4];"
        : "=r"(r[0]), "=r"(r[1]), "=r"(r[2]), "=r"(r[3]) : "r"(addr));
}
__device__ __forceinline__ void ldsm_x4_t(unsigned* r, unsigned addr) {
    asm volatile("ldmatrix.sync.aligned.m8n8.x4.trans.shared.b16 {%0,%1,%2,%3}, [%4];"
        : "=r"(r[0]), "=r"(r[1]), "=r"(r[2]), "=r"(r[3]) : "r"(addr));
}
// split (x,y) into packed bf16x2 hi + residual lo
__device__ __forceinline__ void split2(float x, float y, unsigned& hi, unsigned& lo) {
    __nv_bfloat162 h = __floats2bfloat162_rn(x, y);
    float rx = x - __bfloat162float(h.x);
    float ry = y - __bfloat162float(h.y);
    __nv_bfloat162 l = __floats2bfloat162_rn(rx, ry);
    hi = *(unsigned*)&h;
    lo = *(unsigned*)&l;
}
__device__ __forceinline__ unsigned saddr(const void* p) {
    return (unsigned)__cvta_generic_to_shared(p);
}

// ---------------------------------------------------------------------------
// Weight split+transpose: w[K][N] f32 -> wt_hi/lo [N][K] bf16
// ---------------------------------------------------------------------------
__global__ __launch_bounds__(256) void split_w(
    const float* __restrict__ w, __nv_bfloat16* __restrict__ th,
    __nv_bfloat16* __restrict__ tl, int K, int N)
{
    __shared__ float t[32][33];
    const int k0 = blockIdx.x << 5, n0 = blockIdx.y << 5;
    const int c = threadIdx.x & 31, r8 = threadIdx.x >> 5;
#pragma unroll
    for (int i = 0; i < 4; i++) {
        int k = r8 + (i << 3);
        t[k][c] = w[(size_t)(k0 + k) * N + n0 + c];
    }
    __syncthreads();
#pragma unroll
    for (int i = 0; i < 4; i++) {
        int n = r8 + (i << 3);
        float v = t[c][n];
        __nv_bfloat16 h = __float2bfloat16(v);
        th[(size_t)(n0 + n) * K + k0 + c] = h;
        tl[(size_t)(n0 + n) * K + k0 + c] = __float2bfloat16(v - __bfloat162float(h));
    }
}

// ---------------------------------------------------------------------------
// GEMM split-bf16: C[M,N] = A[M,K]f32 @ W (split bf16 [N][K]) + bias
// 128x128x32 block, 8 warps (2Mx4N), warp 64x32. 3-term mma.
// ---------------------------------------------------------------------------
__global__ __launch_bounds__(256) void gemm_split(
    const float* __restrict__ A,
    const __nv_bfloat16* __restrict__ Wh, const __nv_bfloat16* __restrict__ Wl,
    const float* __restrict__ bias, float* __restrict__ C,
    int M, int N, int K)
{
    __shared__ __nv_bfloat16 As_h[128][40], As_l[128][40];
    __shared__ __nv_bfloat16 Bs_h[128][40], Bs_l[128][40];

    const int tid  = threadIdx.x;
    const int lane = tid & 31;
    const int warp = tid >> 5;
    const int g = lane >> 2, t = lane & 3;
    const int mi = lane >> 3, rr = lane & 7;
    const int aro = ((mi & 1) << 3) + rr, aco = (mi >> 1) << 3;   // A-frag ldsm offs
    const int bno = ((mi >> 1) << 3) + rr, bko = (mi & 1) << 3;   // B-frag ldsm offs
    const int wm = warp >> 2, wn = warp & 3;
    const int bm = blockIdx.y << 7, bn = blockIdx.x << 7;

    const unsigned ash = saddr(As_h), asl = saddr(As_l);
    const unsigned bsh = saddr(Bs_h), bsl = saddr(Bs_l);

    float acc[4][4][4];
#pragma unroll
    for (int i = 0; i < 4; i++)
#pragma unroll
        for (int j = 0; j < 4; j++)
#pragma unroll
            for (int r = 0; r < 4; r++) acc[i][j][r] = 0.f;

    for (int k0 = 0; k0 < K; k0 += 32) {
        // A tile 128x32 f32 -> split bf16
#pragma unroll
        for (int p = 0; p < 4; p++) {
            int idx = tid + (p << 8);
            int r = idx >> 3, c4 = (idx & 7) << 2;
            float4 v = *(const float4*)&A[(size_t)(bm + r) * K + k0 + c4];
            unsigned h01, l01, h23, l23;
            split2(v.x, v.y, h01, l01);
            split2(v.z, v.w, h23, l23);
            *(uint2*)&As_h[r][c4] = make_uint2(h01, h23);
            *(uint2*)&As_l[r][c4] = make_uint2(l01, l23);
        }
        // B tile: [n][k] bf16 straight copy
#pragma unroll
        for (int p = 0; p < 2; p++) {
            int idx = tid + (p << 8);
            int n = idx >> 2, ko = (idx & 3) << 3;
            *(uint4*)&Bs_h[n][ko] = *(const uint4*)&Wh[(size_t)(bn + n) * K + k0 + ko];
            *(uint4*)&Bs_l[n][ko] = *(const uint4*)&Wl[(size_t)(bn + n) * K + k0 + ko];
        }
        __syncthreads();

#pragma unroll
        for (int kc = 0; kc < 2; kc++) {
            unsigned ah[4][4], al[4][4];
#pragma unroll
            for (int mt = 0; mt < 4; mt++) {
                unsigned off = 2u * (((wm << 6) + (mt << 4) + aro) * 40 + (kc << 4) + aco);
                ldsm_x4(ah[mt], ash + off);
                ldsm_x4(al[mt], asl + off);
            }
#pragma unroll
            for (int ntp = 0; ntp < 2; ntp++) {
                unsigned bh[4], bl[4];
                unsigned off = 2u * (((wn << 5) + (ntp << 4) + bno) * 40 + (kc << 4) + bko);
                ldsm_x4(bh, bsh + off);
                ldsm_x4(bl, bsl + off);
#pragma unroll
                for (int hf = 0; hf < 2; hf++) {
                    int nt = (ntp << 1) + hf;
#pragma unroll
                    for (int mt = 0; mt < 4; mt++) mma_bf16(acc[mt][nt], ah[mt], bh + 2*hf);
#pragma unroll
                    for (int mt = 0; mt < 4; mt++) mma_bf16(acc[mt][nt], ah[mt], bl + 2*hf);
#pragma unroll
                    for (int mt = 0; mt < 4; mt++) mma_bf16(acc[mt][nt], al[mt], bh + 2*hf);
                }
            }
        }
        __syncthreads();
    }

    // epilogue
#pragma unroll
    for (int mt = 0; mt < 4; mt++) {
#pragma unroll
        for (int nt = 0; nt < 4; nt++) {
            int row = bm + (wm << 6) + (mt << 4) + g;
            int col = bn + (wn << 5) + (nt << 3) + 2 * t;
            float bx = bias[col], by = bias[col + 1];
            *(float2*)&C[(size_t)row * N + col] =
                make_float2(acc[mt][nt][0] + bx, acc[mt][nt][1] + by);
            *(float2*)&C[(size_t)(row + 8) * N + col] =
                make_float2(acc[mt][nt][2] + bx, acc[mt][nt][3] + by);
        }
    }
}

// ---------------------------------------------------------------------------
// Build `present` [B,2,H,T,64] in d_out
// ---------------------------------------------------------------------------
__global__ void build_present(const float4* __restrict__ past4,
                              const float4* __restrict__ qkv4,
                              float4* __restrict__ pres4)
{
    int i = blockIdx.x * blockDim.x + threadIdx.x;
    int d4  = i & 15;
    int j   = i >> 4;
    int p   = j & (T_ - 1);
    int chh = j >> 12;
    int h = chh & (H_ - 1);
    int c = (chh >> 4) & 1;
    int b = chh >> 5;

    float4 v;
    if (p < P_) {
        v = past4[(((size_t)((b * 2 + c) * H_ + h) * P_ + p) << 4) + d4];
    } else {
        int s = p - P_;
        v = qkv4[(size_t)(b * S_ + s) * 768 + (c + 1) * 256 + h * 16 + d4];
    }
    pres4[i] = v;
}

// ---------------------------------------------------------------------------
// Flash attention, split-bf16 TC. BQ=BK=64, 128 threads (4 warps x 16 rows).
// P stays in registers (S C-frag == PV A-frag layout). V via ldmatrix.trans.
// smem: 6 tiles of [64][72] bf16 = 55296 B (dynamic).
// ---------------------------------------------------------------------------
__global__ __launch_bounds__(128) void flash_split(
    const float* __restrict__ qkv, const float* __restrict__ present,
    float* __restrict__ ctx)
{
    extern __shared__ __nv_bfloat16 smem_bf[];
    __nv_bfloat16* sQh = smem_bf;
    __nv_bfloat16* sQl = sQh + 64 * 72;
    __nv_bfloat16* sKh = sQl + 64 * 72;
    __nv_bfloat16* sKl = sKh + 64 * 72;
    __nv_bfloat16* sVh = sKl + 64 * 72;
    __nv_bfloat16* sVl = sVh + 64 * 72;

    const int tid  = threadIdx.x;
    const int lane = tid & 31;
    const int w    = tid >> 5;
    const int g = lane >> 2, t = lane & 3;
    const int mi = lane >> 3, rr = lane & 7;
    const int aro = ((mi & 1) << 3) + rr, aco = (mi >> 1) << 3;  // Q (A, non-trans)
    const int kno = ((mi >> 1) << 3) + rr, kko = (mi & 1) << 3;  // K (B, non-trans)
    const int vro = ((mi & 1) << 3) + rr, vco = (mi >> 1) << 3;  // V (B, trans)
    const int r0 = (w << 4) + g, r1 = r0 + 8;

    const int bh = blockIdx.y;
    const int b = bh >> 4, h = bh & 15;
    const int qt = gridDim.x - 1 - blockIdx.x;
    const int q0 = qt << 6;

    const float* Qg = qkv + (size_t)(b * S_ + q0) * D3_ + h * 64;
    const float* Kg = present + ((size_t)(b * 2    ) * H_ + h) * T_ * 64;
    const float* Vg = present + ((size_t)(b * 2 + 1) * H_ + h) * T_ * 64;

    const unsigned sqh = saddr(sQh), sql = saddr(sQl);
    const unsigned skh = saddr(sKh), skl = saddr(sKl);
    const unsigned svh = saddr(sVh), svl = saddr(sVl);

    // load + split Q tile (scaled 1/8)
#pragma unroll
    for (int p = 0; p < 8; p++) {
        int idx = tid + (p << 7);
        int r = idx >> 4, c4 = (idx & 15) << 2;
        float4 v = *(const float4*)&Qg[(size_t)r * D3_ + c4];
        v.x *= 0.125f; v.y *= 0.125f; v.z *= 0.125f; v.w *= 0.125f;
        unsigned h01, l01, h23, l23;
        split2(v.x, v.y, h01, l01);
        split2(v.z, v.w, h23, l23);
        *(uint2*)&sQh[r * 72 + c4] = make_uint2(h01, h23);
        *(uint2*)&sQl[r * 72 + c4] = make_uint2(l01, l23);
    }
    __syncthreads();

    // Q fragments: persistent across KV loop
    unsigned qh[4][4], ql[4][4];
#pragma unroll
    for (int kc = 0; kc < 4; kc++) {
        unsigned off = 2u * (((w << 4) + aro) * 72 + (kc << 4) + aco);
        ldsm_x4(qh[kc], sqh + off);
        ldsm_x4(ql[kc], sql + off);
    }

    float m0 = -1e30f, m1 = -1e30f, l0 = 0.f, l1 = 0.f;
    float o[8][4];
#pragma unroll
    for (int nt = 0; nt < 8; nt++)
#pragma unroll
        for (int r = 0; r < 4; r++) o[nt][r] = 0.f;

    const int nIter = (P_ >> 6) + qt + 1;
    for (int it = 0; it < nIter; it++) {
        const int k0 = it << 6;
        __syncthreads();
        // load + split K/V tiles
        {
            const float4* ks4 = (const float4*)(Kg + (size_t)k0 * 64);
            const float4* vs4 = (const float4*)(Vg + (size_t)k0 * 64);
#pragma unroll
            for (int p = 0; p < 8; p++) {
                int idx = tid + (p << 7);
                int r = idx >> 4, c4 = (idx & 15) << 2;
                float4 v = ks4[idx];
                unsigned h01, lo1, h23, lo3;
                split2(v.x, v.y, h01, lo1); split2(v.z, v.w, h23, lo3);
                *(uint2*)&sKh[r * 72 + c4] = make_uint2(h01, h23);
                *(uint2*)&sKl[r * 72 + c4] = make_uint2(lo1, lo3);
                v = vs4[idx];
                split2(v.x, v.y, h01, lo1); split2(v.z, v.w, h23, lo3);
                *(uint2*)&sVh[r * 72 + c4] = make_uint2(h01, h23);
                *(uint2*)&sVl[r * 72 + c4] = make_uint2(lo1, lo3);
            }
        }
        __syncthreads();

        // ---- S = Q K^T ----
        float s[8][4];
#pragma unroll
        for (int nt = 0; nt < 8; nt++)
#pragma unroll
            for (int r = 0; r < 4; r++) s[nt][r] = 0.f;

#pragma unroll
        for (int kc = 0; kc < 4; kc++) {
#pragma unroll
            for (int ntp = 0; ntp < 4; ntp++) {
                unsigned bhh[4], bll[4];
                unsigned off = 2u * (((ntp << 4) + kno) * 72 + (kc << 4) + kko);
                ldsm_x4(bhh, skh + off);
                ldsm_x4(bll, skl + off);
                int nt = ntp << 1;
                mma_bf16(s[nt],     qh[kc], bhh);
                mma_bf16(s[nt + 1], qh[kc], bhh + 2);
                mma_bf16(s[nt],     qh[kc], bll);
                mma_bf16(s[nt + 1], qh[kc], bll + 2);
                mma_bf16(s[nt],     ql[kc], bhh);
                mma_bf16(s[nt + 1], ql[kc], bhh + 2);
            }
        }

        // causal mask on diagonal tile
        if (it == nIter - 1) {
#pragma unroll
            for (int nt = 0; nt < 8; nt++) {
                int c0 = (nt << 3) + 2 * t;
                if (c0     > r0) s[nt][0] = -1e30f;
                if (c0 + 1 > r0) s[nt][1] = -1e30f;
                if (c0     > r1) s[nt][2] = -1e30f;
                if (c0 + 1 > r1) s[nt][3] = -1e30f;
            }
        }

        // ---- online softmax ----
        float mx0 = -1e30f, mx1 = -1e30f;
#pragma unroll
        for (int nt = 0; nt < 8; nt++) {
            mx0 = fmaxf(mx0, fmaxf(s[nt][0], s[nt][1]));
            mx1 = fmaxf(mx1, fmaxf(s[nt][2], s[nt][3]));
        }
        mx0 = fmaxf(mx0, __shfl_xor_sync(0xffffffffu, mx0, 1));
        mx0 = fmaxf(mx0, __shfl_xor_sync(0xffffffffu, mx0, 2));
        mx1 = fmaxf(mx1, __shfl_xor_sync(0xffffffffu, mx1, 1));
        mx1 = fmaxf(mx1, __shfl_xor_sync(0xffffffffu, mx1, 2));
        float nm0 = fmaxf(m0, mx0), nm1 = fmaxf(m1, mx1);
        float sc0 = __expf(m0 - nm0), sc1 = __expf(m1 - nm1);
        float rs0 = 0.f, rs1 = 0.f;
#pragma unroll
        for (int nt = 0; nt < 8; nt++) {
            s[nt][0] = __expf(s[nt][0] - nm0); rs0 += s[nt][0];
            s[nt][1] = __expf(s[nt][1] - nm0); rs0 += s[nt][1];
            s[nt][2] = __expf(s[nt][2] - nm1); rs1 += s[nt][2];
            s[nt][3] = __expf(s[nt][3] - nm1); rs1 += s[nt][3];
        }
        rs0 += __shfl_xor_sync(0xffffffffu, rs0, 1);
        rs0 += __shfl_xor_sync(0xffffffffu, rs0, 2);
        rs1 += __shfl_xor_sync(0xffffffffu, rs1, 1);
        rs1 += __shfl_xor_sync(0xffffffffu, rs1, 2);
        l0 = l0 * sc0 + rs0;  m0 = nm0;
        l1 = l1 * sc1 + rs1;  m1 = nm1;
#pragma unroll
        for (int nt = 0; nt < 8; nt++) {
            o[nt][0] *= sc0; o[nt][1] *= sc0;
            o[nt][2] *= sc1; o[nt][3] *= sc1;
        }

        // ---- O += P V  (P split in registers; S C-frag == PV A-frag) ----
#pragma unroll
        for (int kc = 0; kc < 4; kc++) {
            unsigned ah[4], al[4];
            split2(s[2*kc    ][0], s[2*kc    ][1], ah[0], al[0]);
            split2(s[2*kc    ][2], s[2*kc    ][3], ah[1], al[1]);
            split2(s[2*kc + 1][0], s[2*kc + 1][1], ah[2], al[2]);
            split2(s[2*kc + 1][2], s[2*kc + 1][3], ah[3], al[3]);
#pragma unroll
            for (int ntp = 0; ntp < 4; ntp++) {
                unsigned vh[4], vl[4];
                unsigned off = 2u * (((kc << 4) + vro) * 72 + (ntp << 4) + vco);
                ldsm_x4_t(vh, svh + off);
                ldsm_x4_t(vl, svl + off);
                int nt = ntp << 1;
                mma_bf16(o[nt],     ah, vh);
                mma_bf16(o[nt + 1], ah, vh + 2);
                mma_bf16(o[nt],     ah, vl);
                mma_bf16(o[nt + 1], ah, vl + 2);
                mma_bf16(o[nt],     al, vh);
                mma_bf16(o[nt + 1], al, vh + 2);
            }
        }
    }

    // epilogue
    float inv0 = 1.f / l0, inv1 = 1.f / l1;
    float* d0 = ctx + (size_t)(b * S_ + q0 + r0) * D_ + h * 64;
    float* d1 = ctx + (size_t)(b * S_ + q0 + r1) * D_ + h * 64;
#pragma unroll
    for (int nt = 0; nt < 8; nt++) {
        int c0 = (nt << 3) + 2 * t;
        *(float2*)&d0[c0] = make_float2(o[nt][0] * inv0, o[nt][1] * inv0);
        *(float2*)&d1[c0] = make_float2(o[nt][2] * inv1, o[nt][3] * inv1);
    }
}

// ---------------------------------------------------------------------------
// Launch
// ---------------------------------------------------------------------------
extern "C" void kernel_launch(void* const* d_in, const int* in_sizes, int n_in,
                              void* d_out, int out_size)
{
    const float* x      = (const float*)d_in[0];
    // d_in[1] = mask: exactly causal -> applied analytically
    const float* past   = (const float*)d_in[2];
    const float* w_attn = (const float*)d_in[3];
    const float* b_attn = (const float*)d_in[4];
    const float* w_proj = (const float*)d_in[5];
    const float* b_proj = (const float*)d_in[6];

    float* out     = (float*)d_out;
    float* present = out + OUT_OFF;

    void* p;
    float *qkv, *ctx;
    __nv_bfloat16 *wah, *wal, *wph, *wpl;
    cudaGetSymbolAddress(&p, g_qkv); qkv = (float*)p;
    cudaGetSymbolAddress(&p, g_ctx); ctx = (float*)p;
    cudaGetSymbolAddress(&p, g_wah); wah = (__nv_bfloat16*)p;
    cudaGetSymbolAddress(&p, g_wal); wal = (__nv_bfloat16*)p;
    cudaGetSymbolAddress(&p, g_wph); wph = (__nv_bfloat16*)p;
    cudaGetSymbolAddress(&p, g_wpl); wpl = (__nv_bfloat16*)p;

    const int FLASH_SMEM = 6 * 64 * 72 * 2;   // 55296
    cudaFuncSetAttribute(flash_split,
                         cudaFuncAttributeMaxDynamicSharedMemorySize, FLASH_SMEM);

    // 0. split + transpose weights
    split_w<<<dim3(D_ / 32, D3_ / 32), 256>>>(w_attn, wah, wal, D_, D3_);
    split_w<<<dim3(D_ / 32, D_  / 32), 256>>>(w_proj, wph, wpl, D_, D_);

    // 1. QKV projection
    gemm_split<<<dim3(D3_ / 128, (B_ * S_) / 128), 256>>>(
        x, wah, wal, b_attn, qkv, B_ * S_, D3_, D_);

    // 2. present (KV cache concat) straight into d_out
    build_present<<<(B_ * 2 * H_ * T_ * 16) / 256, 256>>>(
        (const float4*)past, (const float4*)qkv, (float4*)present);

    // 3. flash attention
    flash_split<<<dim3(S_ / 64, B_ * H_), 128, FLASH_SMEM>>>(qkv, present, ctx);

    // 4. output projection
    gemm_split<<<dim3(D_ / 128, (B_ * S_) / 128), 256>>>(
        ctx, wph, wpl, b_proj, out, B_ * S_, D_, D_);
}

// round 5
// speedup vs baseline: 2.9035x; 1.2600x over previous
#include <cuda_runtime.h>
#include <cuda_bf16.h>

// Problem constants
#define B_   2
#define S_   2048
#define D_   1024
#define H_   16
#define P_   2048
#define T_   4096
#define D3_  3072
#define OUT_OFF (B_*S_*D_)

// ---------------------------------------------------------------------------
// Scratch (device globals)
// ---------------------------------------------------------------------------
__device__ float g_qkv[(size_t)B_ * S_ * D3_];
__device__ __nv_bfloat16 g_xh [(size_t)B_ * S_ * D_];    // x split hi
__device__ __nv_bfloat16 g_xl [(size_t)B_ * S_ * D_];    // x split lo
__device__ __nv_bfloat16 g_ch [(size_t)B_ * S_ * D_];    // ctx split hi
__device__ __nv_bfloat16 g_cl [(size_t)B_ * S_ * D_];    // ctx split lo
__device__ __nv_bfloat16 g_kvh[(size_t)B_ * 2 * H_ * T_ * 64];  // K/V hi
__device__ __nv_bfloat16 g_kvl[(size_t)B_ * 2 * H_ * T_ * 64];  // K/V lo
__device__ __nv_bfloat16 g_wah[(size_t)D3_ * D_];   // w_attn^T hi [N][K]
__device__ __nv_bfloat16 g_wal[(size_t)D3_ * D_];
__device__ __nv_bfloat16 g_wph[(size_t)D_ * D_];    // w_proj^T hi
__device__ __nv_bfloat16 g_wpl[(size_t)D_ * D_];

// ---------------------------------------------------------------------------
// Primitives
// ---------------------------------------------------------------------------
__device__ __forceinline__ void mma_bf16(float* d, const unsigned* a, const unsigned* b) {
    asm volatile(
        "mma.sync.aligned.m16n8k16.row.col.f32.bf16.bf16.f32 "
        "{%0,%1,%2,%3}, {%4,%5,%6,%7}, {%8,%9}, {%0,%1,%2,%3};\n"
        : "+f"(d[0]), "+f"(d[1]), "+f"(d[2]), "+f"(d[3])
        : "r"(a[0]), "r"(a[1]), "r"(a[2]), "r"(a[3]), "r"(b[0]), "r"(b[1]));
}
__device__ __forceinline__ void ldsm_x4(unsigned* r, unsigned addr) {
    asm volatile("ldmatrix.sync.aligned.m8n8.x4.shared.b16 {%0,%1,%2,%3}, [%4];"
        : "=r"(r[0]), "=r"(r[1]), "=r"(r[2]), "=r"(r[3]) : "r"(addr));
}
__device__ __forceinline__ void ldsm_x4_t(unsigned* r, unsigned addr) {
    asm volatile("ldmatrix.sync.aligned.m8n8.x4.trans.shared.b16 {%0,%1,%2,%3}, [%4];"
        : "=r"(r[0]), "=r"(r[1]), "=r"(r[2]), "=r"(r[3]) : "r"(addr));
}
__device__ __forceinline__ void split2(float x, float y, unsigned& hi, unsigned& lo) {
    __nv_bfloat162 h = __floats2bfloat162_rn(x, y);
    float rx = x - __bfloat162float(h.x);
    float ry = y - __bfloat162float(h.y);
    __nv_bfloat162 l = __floats2bfloat162_rn(rx, ry);
    hi = *(unsigned*)&h;
    lo = *(unsigned*)&l;
}
__device__ __forceinline__ unsigned saddr(const void* p) {
    return (unsigned)__cvta_generic_to_shared(p);
}
__device__ __forceinline__ void cp16(unsigned dst, const void* src) {
    asm volatile("cp.async.cg.shared.global [%0], [%1], 16;\n" :: "r"(dst), "l"(src));
}
__device__ __forceinline__ void cp_commit() {
    asm volatile("cp.async.commit_group;\n");
}
template<int N> __device__ __forceinline__ void cp_wait() {
    asm volatile("cp.async.wait_group %0;\n" :: "n"(N));
}

// ---------------------------------------------------------------------------
// Split x -> bf16 hi/lo (one pass)
// ---------------------------------------------------------------------------
__global__ void split_x(const float4* __restrict__ x4,
                        __nv_bfloat16* __restrict__ xh,
                        __nv_bfloat16* __restrict__ xl)
{
    int i = blockIdx.x * blockDim.x + threadIdx.x;   // 1M float4
    float4 v = x4[i];
    unsigned h01, l01, h23, l23;
    split2(v.x, v.y, h01, l01);
    split2(v.z, v.w, h23, l23);
    *(uint2*)&xh[(size_t)i * 4] = make_uint2(h01, h23);
    *(uint2*)&xl[(size_t)i * 4] = make_uint2(l01, l23);
}

// ---------------------------------------------------------------------------
// Weight split+transpose: w[K][N] f32 -> wt_hi/lo [N][K] bf16
// ---------------------------------------------------------------------------
__global__ __launch_bounds__(256) void split_w(
    const float* __restrict__ w, __nv_bfloat16* __restrict__ th,
    __nv_bfloat16* __restrict__ tl, int K, int N)
{
    __shared__ float t[32][33];
    const int k0 = blockIdx.x << 5, n0 = blockIdx.y << 5;
    const int c = threadIdx.x & 31, r8 = threadIdx.x >> 5;
#pragma unroll
    for (int i = 0; i < 4; i++) {
        int k = r8 + (i << 3);
        t[k][c] = w[(size_t)(k0 + k) * N + n0 + c];
    }
    __syncthreads();
#pragma unroll
    for (int i = 0; i < 4; i++) {
        int n = r8 + (i << 3);
        float v = t[c][n];
        __nv_bfloat16 h = __float2bfloat16(v);
        th[(size_t)(n0 + n) * K + k0 + c] = h;
        tl[(size_t)(n0 + n) * K + k0 + c] = __float2bfloat16(v - __bfloat162float(h));
    }
}

// ---------------------------------------------------------------------------
// Build `present` f32 + split K/V bf16 hi/lo
// ---------------------------------------------------------------------------
__global__ void build_present(const float4* __restrict__ past4,
                              const float4* __restrict__ qkv4,
                              float4* __restrict__ pres4,
                              __nv_bfloat16* __restrict__ kvh,
                              __nv_bfloat16* __restrict__ kvl)
{
    int i = blockIdx.x * blockDim.x + threadIdx.x;   // over float4 of present
    int d4  = i & 15;
    int j   = i >> 4;
    int p   = j & (T_ - 1);
    int chh = j >> 12;
    int h = chh & (H_ - 1);
    int c = (chh >> 4) & 1;
    int b = chh >> 5;

    float4 v;
    if (p < P_) {
        v = past4[(((size_t)((b * 2 + c) * H_ + h) * P_ + p) << 4) + d4];
    } else {
        int s = p - P_;
        v = qkv4[(size_t)(b * S_ + s) * 768 + (c + 1) * 256 + h * 16 + d4];
    }
    pres4[i] = v;
    unsigned h01, l01, h23, l23;
    split2(v.x, v.y, h01, l01);
    split2(v.z, v.w, h23, l23);
    *(uint2*)&kvh[(size_t)i * 4] = make_uint2(h01, h23);
    *(uint2*)&kvl[(size_t)i * 4] = make_uint2(l01, l23);
}

// ---------------------------------------------------------------------------
// GEMM, pre-split operands, cp.async 2-stage.
// C[M,N] = (Ah+Al)[M,K] @ (Wh+Wl)[N,K]^T + bias   (3-term)
// stage layout (bytes): As_h 0, As_l 10240, Bs_h 20480, Bs_l 30720 (stride 80B)
// ---------------------------------------------------------------------------
__global__ __launch_bounds__(256, 2) void gemm_presplit(
    const __nv_bfloat16* __restrict__ Ah, const __nv_bfloat16* __restrict__ Al,
    const __nv_bfloat16* __restrict__ Wh, const __nv_bfloat16* __restrict__ Wl,
    const float* __restrict__ bias, float* __restrict__ C,
    int M, int N, int K)
{
    extern __shared__ char sg[];
    const unsigned sb = saddr(sg);

    const int tid  = threadIdx.x;
    const int lane = tid & 31;
    const int warp = tid >> 5;
    const int g = lane >> 2, t = lane & 3;
    const int mi = lane >> 3, rr = lane & 7;
    const int aro = ((mi & 1) << 3) + rr, aco = (mi >> 1) << 3;
    const int bno = ((mi >> 1) << 3) + rr, bko = (mi & 1) << 3;
    const int wm = warp >> 2, wn = warp & 3;
    const int bm = blockIdx.y << 7, bn = blockIdx.x << 7;

    auto issue = [&](int k0, int st) {
        unsigned b0 = sb + st * 40960;
#pragma unroll
        for (int p = 0; p < 2; p++) {
            int idx = tid + (p << 8);
            int r = idx >> 2, cb = (idx & 3) << 4;   // row, byte col
            size_t ga = ((size_t)(bm + r) * K + k0) * 2 + cb;
            size_t gb = ((size_t)(bn + r) * K + k0) * 2 + cb;
            unsigned d = b0 + r * 80 + cb;
            cp16(d,         (const char*)Ah + ga);
            cp16(d + 10240, (const char*)Al + ga);
            cp16(d + 20480, (const char*)Wh + gb);
            cp16(d + 30720, (const char*)Wl + gb);
        }
    };

    float acc[4][4][4];
#pragma unroll
    for (int i = 0; i < 4; i++)
#pragma unroll
        for (int j = 0; j < 4; j++)
#pragma unroll
            for (int r = 0; r < 4; r++) acc[i][j][r] = 0.f;

    const int nK = K >> 5;
    issue(0, 0);
    cp_commit();

    for (int it = 0; it < nK; it++) {
        if (it + 1 < nK) { issue((it + 1) << 5, (it + 1) & 1); cp_commit(); cp_wait<1>(); }
        else             { cp_wait<0>(); }
        __syncthreads();

        unsigned b0 = sb + (it & 1) * 40960;
#pragma unroll
        for (int kc = 0; kc < 2; kc++) {
            unsigned ah[4][4], al[4][4];
#pragma unroll
            for (int mt = 0; mt < 4; mt++) {
                unsigned off = b0 + (unsigned)((((wm << 6) + (mt << 4) + aro) * 40 + (kc << 4) + aco) * 2);
                ldsm_x4(ah[mt], off);
                ldsm_x4(al[mt], off + 10240);
            }
#pragma unroll
            for (int ntp = 0; ntp < 2; ntp++) {
                unsigned bh[4], bl[4];
                unsigned off = b0 + 20480 + (unsigned)((((wn << 5) + (ntp << 4) + bno) * 40 + (kc << 4) + bko) * 2);
                ldsm_x4(bh, off);
                ldsm_x4(bl, off + 10240);
#pragma unroll
                for (int hf = 0; hf < 2; hf++) {
                    int nt = (ntp << 1) + hf;
#pragma unroll
                    for (int mt = 0; mt < 4; mt++) mma_bf16(acc[mt][nt], ah[mt], bh + 2*hf);
#pragma unroll
                    for (int mt = 0; mt < 4; mt++) mma_bf16(acc[mt][nt], ah[mt], bl + 2*hf);
#pragma unroll
                    for (int mt = 0; mt < 4; mt++) mma_bf16(acc[mt][nt], al[mt], bh + 2*hf);
                }
            }
        }
        __syncthreads();
    }

    // epilogue
#pragma unroll
    for (int mt = 0; mt < 4; mt++) {
#pragma unroll
        for (int nt = 0; nt < 4; nt++) {
            int row = bm + (wm << 6) + (mt << 4) + g;
            int col = bn + (wn << 5) + (nt << 3) + 2 * t;
            float bx = bias[col], by = bias[col + 1];
            *(float2*)&C[(size_t)row * N + col] =
                make_float2(acc[mt][nt][0] + bx, acc[mt][nt][1] + by);
            *(float2*)&C[(size_t)(row + 8) * N + col] =
                make_float2(acc[mt][nt][2] + bx, acc[mt][nt][3] + by);
        }
    }
}

// ---------------------------------------------------------------------------
// Flash attention: pre-split K/V, cp.async 2-stage, P in registers.
// stage st (bytes): Kh st*36864+0, Kl +9216, Vh +18432, Vl +27648
// tile = [64][72] bf16 (9216 B, row stride 144 B). Q aliases stage 0.
// total smem 73728 B.
// ---------------------------------------------------------------------------
__global__ __launch_bounds__(128) void flash_presplit(
    const float* __restrict__ qkv,
    const __nv_bfloat16* __restrict__ kvh, const __nv_bfloat16* __restrict__ kvl,
    __nv_bfloat16* __restrict__ ctxh, __nv_bfloat16* __restrict__ ctxl)
{
    extern __shared__ char sf[];
    const unsigned sb = saddr(sf);

    const int tid  = threadIdx.x;
    const int lane = tid & 31;
    const int w    = tid >> 5;
    const int g = lane >> 2, t = lane & 3;
    const int mi = lane >> 3, rr = lane & 7;
    const int aro = ((mi & 1) << 3) + rr, aco = (mi >> 1) << 3;  // Q (A)
    const int kno = ((mi >> 1) << 3) + rr, kko = (mi & 1) << 3;  // K (B)
    const int vro = ((mi & 1) << 3) + rr, vco = (mi >> 1) << 3;  // V (B, trans)
    const int r0 = (w << 4) + g, r1 = r0 + 8;

    const int bh = blockIdx.y;
    const int b = bh >> 4, h = bh & 15;
    const int qt = gridDim.x - 1 - blockIdx.x;
    const int q0 = qt << 6;

    const float* Qg = qkv + (size_t)(b * S_ + q0) * D3_ + h * 64;
    const __nv_bfloat16* Kgh = kvh + ((size_t)(b * 2    ) * H_ + h) * T_ * 64;
    const __nv_bfloat16* Kgl = kvl + ((size_t)(b * 2    ) * H_ + h) * T_ * 64;
    const __nv_bfloat16* Vgh = kvh + ((size_t)(b * 2 + 1) * H_ + h) * T_ * 64;
    const __nv_bfloat16* Vgl = kvl + ((size_t)(b * 2 + 1) * H_ + h) * T_ * 64;

    // ---- Q: load f32, scale, split into stage-0 region (aliased) ----
    __nv_bfloat16* sQh = (__nv_bfloat16*)sf;
    __nv_bfloat16* sQl = (__nv_bfloat16*)(sf + 9216);
#pragma unroll
    for (int p = 0; p < 8; p++) {
        int idx = tid + (p << 7);
        int r = idx >> 4, c4 = (idx & 15) << 2;
        float4 v = *(const float4*)&Qg[(size_t)r * D3_ + c4];
        v.x *= 0.125f; v.y *= 0.125f; v.z *= 0.125f; v.w *= 0.125f;
        unsigned h01, l01, h23, l23;
        split2(v.x, v.y, h01, l01);
        split2(v.z, v.w, h23, l23);
        *(uint2*)&sQh[r * 72 + c4] = make_uint2(h01, h23);
        *(uint2*)&sQl[r * 72 + c4] = make_uint2(l01, l23);
    }
    __syncthreads();

    unsigned qh[4][4], ql[4][4];
#pragma unroll
    for (int kc = 0; kc < 4; kc++) {
        unsigned off = sb + (unsigned)((((w << 4) + aro) * 72 + (kc << 4) + aco) * 2);
        ldsm_x4(qh[kc], off);
        ldsm_x4(ql[kc], off + 9216);
    }
    __syncthreads();   // Q frags in regs; stage 0 may now be overwritten

    auto issueKV = [&](int k0, int st) {
        unsigned b0 = sb + st * 36864;
        size_t gr = (size_t)k0 * 128;    // byte offset of row k0
#pragma unroll
        for (int p = 0; p < 4; p++) {
            int idx = tid + (p << 7);
            int r = idx >> 3, cb = (idx & 7) << 4;
            unsigned d = b0 + r * 144 + cb;
            size_t go = gr + (size_t)r * 128 + cb;
            cp16(d,         (const char*)Kgh + go);
            cp16(d +  9216, (const char*)Kgl + go);
            cp16(d + 18432, (const char*)Vgh + go);
            cp16(d + 27648, (const char*)Vgl + go);
        }
    };

    float m0 = -1e30f, m1 = -1e30f, l0 = 0.f, l1 = 0.f;
    float o[8][4];
#pragma unroll
    for (int nt = 0; nt < 8; nt++)
#pragma unroll
        for (int r = 0; r < 4; r++) o[nt][r] = 0.f;

    const int nIter = (P_ >> 6) + qt + 1;
    issueKV(0, 0);
    cp_commit();

    for (int it = 0; it < nIter; it++) {
        if (it + 1 < nIter) { issueKV((it + 1) << 6, (it + 1) & 1); cp_commit(); cp_wait<1>(); }
        else                { cp_wait<0>(); }
        __syncthreads();

        unsigned kb = sb + (it & 1) * 36864;

        // ---- S = Q K^T ----
        float s[8][4];
#pragma unroll
        for (int nt = 0; nt < 8; nt++)
#pragma unroll
            for (int r = 0; r < 4; r++) s[nt][r] = 0.f;

#pragma unroll
        for (int kc = 0; kc < 4; kc++) {
#pragma unroll
            for (int ntp = 0; ntp < 4; ntp++) {
                unsigned bhh[4], bll[4];
                unsigned off = kb + (unsigned)((((ntp << 4) + kno) * 72 + (kc << 4) + kko) * 2);
                ldsm_x4(bhh, off);
                ldsm_x4(bll, off + 9216);
                int nt = ntp << 1;
                mma_bf16(s[nt],     qh[kc], bhh);
                mma_bf16(s[nt + 1], qh[kc], bhh + 2);
                mma_bf16(s[nt],     qh[kc], bll);
                mma_bf16(s[nt + 1], qh[kc], bll + 2);
                mma_bf16(s[nt],     ql[kc], bhh);
                mma_bf16(s[nt + 1], ql[kc], bhh + 2);
            }
        }

        // causal mask on diagonal tile
        if (it == nIter - 1) {
#pragma unroll
            for (int nt = 0; nt < 8; nt++) {
                int c0 = (nt << 3) + 2 * t;
                if (c0     > r0) s[nt][0] = -1e30f;
                if (c0 + 1 > r0) s[nt][1] = -1e30f;
                if (c0     > r1) s[nt][2] = -1e30f;
                if (c0 + 1 > r1) s[nt][3] = -1e30f;
            }
        }

        // ---- online softmax ----
        float mx0 = -1e30f, mx1 = -1e30f;
#pragma unroll
        for (int nt = 0; nt < 8; nt++) {
            mx0 = fmaxf(mx0, fmaxf(s[nt][0], s[nt][1]));
            mx1 = fmaxf(mx1, fmaxf(s[nt][2], s[nt][3]));
        }
        mx0 = fmaxf(mx0, __shfl_xor_sync(0xffffffffu, mx0, 1));
        mx0 = fmaxf(mx0, __shfl_xor_sync(0xffffffffu, mx0, 2));
        mx1 = fmaxf(mx1, __shfl_xor_sync(0xffffffffu, mx1, 1));
        mx1 = fmaxf(mx1, __shfl_xor_sync(0xffffffffu, mx1, 2));
        float nm0 = fmaxf(m0, mx0), nm1 = fmaxf(m1, mx1);
        float sc0 = __expf(m0 - nm0), sc1 = __expf(m1 - nm1);
        float rs0 = 0.f, rs1 = 0.f;
#pragma unroll
        for (int nt = 0; nt < 8; nt++) {
            s[nt][0] = __expf(s[nt][0] - nm0); rs0 += s[nt][0];
            s[nt][1] = __expf(s[nt][1] - nm0); rs0 += s[nt][1];
            s[nt][2] = __expf(s[nt][2] - nm1); rs1 += s[nt][2];
            s[nt][3] = __expf(s[nt][3] - nm1); rs1 += s[nt][3];
        }
        rs0 += __shfl_xor_sync(0xffffffffu, rs0, 1);
        rs0 += __shfl_xor_sync(0xffffffffu, rs0, 2);
        rs1 += __shfl_xor_sync(0xffffffffu, rs1, 1);
        rs1 += __shfl_xor_sync(0xffffffffu, rs1, 2);
        l0 = l0 * sc0 + rs0;  m0 = nm0;
        l1 = l1 * sc1 + rs1;  m1 = nm1;
#pragma unroll
        for (int nt = 0; nt < 8; nt++) {
            o[nt][0] *= sc0; o[nt][1] *= sc0;
            o[nt][2] *= sc1; o[nt][3] *= sc1;
        }

        // ---- O += P V  (P split in registers) ----
#pragma unroll
        for (int kc = 0; kc < 4; kc++) {
            unsigned ah[4], al[4];
            split2(s[2*kc    ][0], s[2*kc    ][1], ah[0], al[0]);
            split2(s[2*kc    ][2], s[2*kc    ][3], ah[1], al[1]);
            split2(s[2*kc + 1][0], s[2*kc + 1][1], ah[2], al[2]);
            split2(s[2*kc + 1][2], s[2*kc + 1][3], ah[3], al[3]);
#pragma unroll
            for (int ntp = 0; ntp < 4; ntp++) {
                unsigned vh[4], vl[4];
                unsigned off = kb + 18432 + (unsigned)((((kc << 4) + vro) * 72 + (ntp << 4) + vco) * 2);
                ldsm_x4_t(vh, off);
                ldsm_x4_t(vl, off + 9216);
                int nt = ntp << 1;
                mma_bf16(o[nt],     ah, vh);
                mma_bf16(o[nt + 1], ah, vh + 2);
                mma_bf16(o[nt],     ah, vl);
                mma_bf16(o[nt + 1], ah, vl + 2);
                mma_bf16(o[nt],     al, vh);
                mma_bf16(o[nt + 1], al, vh + 2);
            }
        }
        __syncthreads();   // all warps done with this stage before reuse
    }

    // epilogue: normalize + split-write ctx hi/lo
    float inv0 = 1.f / l0, inv1 = 1.f / l1;
    size_t o0 = (size_t)(b * S_ + q0 + r0) * D_ + h * 64;
    size_t o1 = (size_t)(b * S_ + q0 + r1) * D_ + h * 64;
#pragma unroll
    for (int nt = 0; nt < 8; nt++) {
        int c0 = (nt << 3) + 2 * t;
        unsigned hh, ll;
        split2(o[nt][0] * inv0, o[nt][1] * inv0, hh, ll);
        *(unsigned*)&ctxh[o0 + c0] = hh;
        *(unsigned*)&ctxl[o0 + c0] = ll;
        split2(o[nt][2] * inv1, o[nt][3] * inv1, hh, ll);
        *(unsigned*)&ctxh[o1 + c0] = hh;
        *(unsigned*)&ctxl[o1 + c0] = ll;
    }
}

// ---------------------------------------------------------------------------
// Launch
// ---------------------------------------------------------------------------
extern "C" void kernel_launch(void* const* d_in, const int* in_sizes, int n_in,
                              void* d_out, int out_size)
{
    const float* x      = (const float*)d_in[0];
    // d_in[1] = mask: exactly causal -> applied analytically
    const float* past   = (const float*)d_in[2];
    const float* w_attn = (const float*)d_in[3];
    const float* b_attn = (const float*)d_in[4];
    const float* w_proj = (const float*)d_in[5];
    const float* b_proj = (const float*)d_in[6];

    float* out     = (float*)d_out;
    float* present = out + OUT_OFF;

    void* p;
    float* qkv;
    __nv_bfloat16 *xh, *xl, *ch, *cl, *kvh, *kvl, *wah, *wal, *wph, *wpl;
    cudaGetSymbolAddress(&p, g_qkv); qkv = (float*)p;
    cudaGetSymbolAddress(&p, g_xh);  xh  = (__nv_bfloat16*)p;
    cudaGetSymbolAddress(&p, g_xl);  xl  = (__nv_bfloat16*)p;
    cudaGetSymbolAddress(&p, g_ch);  ch  = (__nv_bfloat16*)p;
    cudaGetSymbolAddress(&p, g_cl);  cl  = (__nv_bfloat16*)p;
    cudaGetSymbolAddress(&p, g_kvh); kvh = (__nv_bfloat16*)p;
    cudaGetSymbolAddress(&p, g_kvl); kvl = (__nv_bfloat16*)p;
    cudaGetSymbolAddress(&p, g_wah); wah = (__nv_bfloat16*)p;
    cudaGetSymbolAddress(&p, g_wal); wal = (__nv_bfloat16*)p;
    cudaGetSymbolAddress(&p, g_wph); wph = (__nv_bfloat16*)p;
    cudaGetSymbolAddress(&p, g_wpl); wpl = (__nv_bfloat16*)p;

    const int GEMM_SMEM  = 2 * 40960;   // 81920
    const int FLASH_SMEM = 2 * 36864;   // 73728
    cudaFuncSetAttribute(gemm_presplit,
                         cudaFuncAttributeMaxDynamicSharedMemorySize, GEMM_SMEM);
    cudaFuncSetAttribute(flash_presplit,
                         cudaFuncAttributeMaxDynamicSharedMemorySize, FLASH_SMEM);

    // 0. pre-split inputs/weights
    split_x<<<(B_ * S_ * D_ / 4) / 256, 256>>>((const float4*)x, xh, xl);
    split_w<<<dim3(D_ / 32, D3_ / 32), 256>>>(w_attn, wah, wal, D_, D3_);
    split_w<<<dim3(D_ / 32, D_  / 32), 256>>>(w_proj, wph, wpl, D_, D_);

    // 1. QKV projection
    gemm_presplit<<<dim3(D3_ / 128, (B_ * S_) / 128), 256, GEMM_SMEM>>>(
        xh, xl, wah, wal, b_attn, qkv, B_ * S_, D3_, D_);

    // 2. present (f32, into d_out) + K/V hi/lo split
    build_present<<<(B_ * 2 * H_ * T_ * 16) / 256, 256>>>(
        (const float4*)past, (const float4*)qkv, (float4*)present, kvh, kvl);

    // 3. flash attention -> ctx hi/lo
    flash_presplit<<<dim3(S_ / 64, B_ * H_), 128, FLASH_SMEM>>>(
        qkv, kvh, kvl, ch, cl);

    // 4. output projection
    gemm_presplit<<<dim3(D_ / 128, (B_ * S_) / 128), 256, GEMM_SMEM>>>(
        ch, cl, wph, wpl, b_proj, out, B_ * S_, D_, D_);
}